// round 7
// baseline (speedup 1.0000x reference)
#include <cuda_runtime.h>
#include <math.h>

// Problem constants (fixed shapes from the reference)
#define HH 64
#define WW 96
#define DD 64
#define BB 1
#define VV 4
#define CC 16
#define EPSF 1e-8f

// -------- device scratch (allocation-free per harness rules) --------
__device__ float g_P[VV * 12];          // (K @ E)[:3,:] per view, row-major 3x4
__device__ float g_invK[9];             // cur_invK[:3,:3]
__device__ float g_depth[DD];           // inverse-depth-interpolated planes
__device__ float g_srcT[VV * HH * WW * CC];  // src feats transposed to (V,H,W,C)
__device__ float g_curT[HH * WW * CC];       // cur feats transposed to (H,W,C)

// -------- setup: P = K@E (rows 0..2), invK, depth planes --------
__global__ void setup_kernel(const float* __restrict__ src_extrinsics, // (B,V,4,4)
                             const float* __restrict__ src_Ks,         // (B,V,4,4)
                             const float* __restrict__ cur_invK,       // (B,4,4)
                             const float* __restrict__ min_depth,
                             const float* __restrict__ max_depth) {
    int tid = threadIdx.x;  // 64 threads

    // depth planes
    {
        float mind = min_depth[0];
        float maxd = max_depth[0];
        float inv_min = 1.0f / mind;
        float inv_max = 1.0f / maxd;
        float ramp = (float)tid / (float)(DD - 1);
        g_depth[tid] = 1.0f / (inv_min + (inv_max - inv_min) * ramp);
    }

    if (tid < VV) {
        const float* K = src_Ks + tid * 16;
        const float* E = src_extrinsics + tid * 16;
        #pragma unroll
        for (int i = 0; i < 3; i++) {
            #pragma unroll
            for (int j = 0; j < 4; j++) {
                float s = 0.0f;
                #pragma unroll
                for (int k = 0; k < 4; k++) s += K[i * 4 + k] * E[k * 4 + j];
                g_P[tid * 12 + i * 4 + j] = s;
            }
        }
    }
    if (tid == 0) {
        #pragma unroll
        for (int r = 0; r < 3; r++)
            #pragma unroll
            for (int c = 0; c < 3; c++)
                g_invK[r * 3 + c] = cur_invK[r * 4 + c];
    }
}

// -------- transpose (V,C,H,W)->(V,H,W,C) and (C,H,W)->(H,W,C), smem-tiled --------
// One block per (v,h) row slab (or per h for cur). Conflict-free via pad-17.
__global__ void transpose_kernel(const float* __restrict__ src_feats,
                                 const float* __restrict__ cur_feats) {
    __shared__ float sh[WW * 17];  // [w][c] with pad
    int b = blockIdx.x;
    int tid = threadIdx.x;  // 256 threads

    const float* in;
    float* out;
    if (b < VV * HH) {
        int v = b >> 6;          // /HH
        int h = b & (HH - 1);
        in  = src_feats + ((size_t)v * CC) * (HH * WW) + (size_t)h * WW;
        out = g_srcT + ((size_t)(v * HH + h) * WW) * CC;
    } else {
        int h = b - VV * HH;
        in  = cur_feats + (size_t)h * WW;
        out = g_curT + ((size_t)h * WW) * CC;
    }

    // load: i = c*WW + w  (coalesced along w), write sh[w*17 + c]
    #pragma unroll
    for (int i = tid; i < CC * WW; i += 256) {
        int c = i / WW;
        int w = i - c * WW;
        sh[w * 17 + c] = in[(size_t)c * (HH * WW) + w];
    }
    __syncthreads();
    // store: j -> (w = j>>4, c = j&15), contiguous writes
    #pragma unroll
    for (int j = tid; j < WW * CC; j += 256) {
        int w = j >> 4;
        int c = j & 15;
        out[j] = sh[w * 17 + c];
    }
}

// -------- main cost-volume kernel: one thread per (d,h,w) --------
__global__ void __launch_bounds__(128) cost_kernel(float* __restrict__ out) {
    __shared__ float sP[VV * 12];
    __shared__ float sIK[9];
    int tid = threadIdx.x;
    if (tid < VV * 12) sP[tid] = g_P[tid];
    if (tid < 9) sIK[tid] = g_invK[tid];
    __syncthreads();

    int idx = blockIdx.x * 128 + tid;   // grid sized exactly: D*H*W / 128
    int w = idx % WW;
    int t = idx / WW;
    int h = t % HH;
    int d = t / HH;

    float depth = g_depth[d];

    // ray = invK[:3,:3] @ (w+0.5, h+0.5, 1)
    float px = (float)w + 0.5f;
    float py = (float)h + 0.5f;
    float rx = sIK[0] * px + sIK[1] * py + sIK[2];
    float ry = sIK[3] * px + sIK[4] * py + sIK[5];
    float rz = sIK[6] * px + sIK[7] * py + sIK[8];

    // cur feature vector (16 ch), contiguous
    const float4* curp = (const float4*)(g_curT + ((size_t)(h * WW + w) << 4));
    float4 c0 = curp[0], c1 = curp[1], c2 = curp[2], c3 = curp[3];

    float acc = 0.0f;

    #pragma unroll
    for (int v = 0; v < VV; v++) {
        const float* P = sP + v * 12;
        float qx = P[0] * rx + P[1] * ry + P[2]  * rz;
        float qy = P[4] * rx + P[5] * ry + P[6]  * rz;
        float qz = P[8] * rx + P[9] * ry + P[10] * rz;
        float cx = fmaf(qx, depth, P[3]);
        float cy = fmaf(qy, depth, P[7]);
        float cz = fmaf(qz, depth, P[11]);

        if (cz > 0.0f) {
            float inv = 1.0f / (cz + EPSF);
            float u  = cx * inv;
            float vv = cy * inv;
            // replicate reference arithmetic exactly
            float un = 2.0f * u  * (1.0f / (float)WW) - 1.0f;
            float vn = 2.0f * vv * (1.0f / (float)HH) - 1.0f;
            float x = (un + 1.0f) * ((float)WW * 0.5f) - 0.5f;
            float y = (vn + 1.0f) * ((float)HH * 0.5f) - 0.5f;

            float x0f = floorf(x);
            float y0f = floorf(y);

            float accv = 0.0f;
            const float* srcv = g_srcT + ((size_t)v * HH * WW << 4);

            #pragma unroll
            for (int dy = 0; dy < 2; dy++) {
                float yif = y0f + (float)dy;
                bool vy = (yif >= 0.0f) && (yif < (float)HH);
                float wy = 1.0f - fabsf(y - yif);
                #pragma unroll
                for (int dx = 0; dx < 2; dx++) {
                    float xif = x0f + (float)dx;
                    bool vx = (xif >= 0.0f) && (xif < (float)WW);
                    if (vy && vx) {
                        float wgt = (1.0f - fabsf(x - xif)) * wy;
                        int xi = (int)xif;
                        int yi = (int)yif;
                        const float4* sp =
                            (const float4*)(srcv + ((size_t)(yi * WW + xi) << 4));
                        float4 s0 = sp[0], s1 = sp[1], s2 = sp[2], s3 = sp[3];
                        float dt;
                        dt  = s0.x * c0.x; dt = fmaf(s0.y, c0.y, dt);
                        dt = fmaf(s0.z, c0.z, dt); dt = fmaf(s0.w, c0.w, dt);
                        dt = fmaf(s1.x, c1.x, dt); dt = fmaf(s1.y, c1.y, dt);
                        dt = fmaf(s1.z, c1.z, dt); dt = fmaf(s1.w, c1.w, dt);
                        dt = fmaf(s2.x, c2.x, dt); dt = fmaf(s2.y, c2.y, dt);
                        dt = fmaf(s2.z, c2.z, dt); dt = fmaf(s2.w, c2.w, dt);
                        dt = fmaf(s3.x, c3.x, dt); dt = fmaf(s3.y, c3.y, dt);
                        dt = fmaf(s3.z, c3.z, dt); dt = fmaf(s3.w, c3.w, dt);
                        accv = fmaf(wgt, dt, accv);
                    }
                }
            }
            acc += accv;
        }
    }

    out[idx] = acc;
}

extern "C" void kernel_launch(void* const* d_in, const int* in_sizes, int n_in,
                              void* d_out, int out_size) {
    const float* cur_feats      = (const float*)d_in[0];  // (B,C,H,W)
    const float* src_feats      = (const float*)d_in[1];  // (B,V,C,H,W)
    const float* src_extrinsics = (const float*)d_in[2];  // (B,V,4,4)
    const float* src_Ks         = (const float*)d_in[3];  // (B,V,4,4)
    const float* cur_invK       = (const float*)d_in[4];  // (B,4,4)
    const float* min_depth      = (const float*)d_in[5];
    const float* max_depth      = (const float*)d_in[6];
    float* out = (float*)d_out;

    setup_kernel<<<1, 64>>>(src_extrinsics, src_Ks, cur_invK, min_depth, max_depth);
    transpose_kernel<<<VV * HH + HH, 256>>>(src_feats, cur_feats);

    int total = DD * HH * WW;          // 393216, divisible by 128
    cost_kernel<<<total / 128, 128>>>(out);
}